// round 3
// baseline (speedup 1.0000x reference)
#include <cuda_runtime.h>
#include <cuda_bf16.h>

// HMM forward, scaled probability domain.
//   w_t[j] = (sum_i w_{t-1}[i] * exp(trans[i,j])) * inv_norm * exp(emit[j,obs[t]])
//   out    = log(sum_j w_final[j]) + sum log(norm)
//
// 128 persistent CTAs (one wave), 256 threads each; CTA owns 8 output columns.
// Sync: NO counters/atomics. w values are strictly positive; each stored word
// carries the step phase in its SIGN BIT (buffer = t&1, sign = (t>>1)&1).
// Polling the data IS the synchronization (proven in R2). Buffer reuse at
// distance 4 cannot race: the writer of step t+4 data-depends transitively on
// the reader's own t+1 output, which is written only after its t read finished.
//
// Layout: thread tid polls granule w[4*tid..4*tid+3] — exactly the 4 source
// states its GEMV needs. Its P slice (8 cols x 4 sources = 32 floats) lives
// in registers. Hot loop: poll -> 32 FFMA -> shfl butterfly (8 accs) ->
// STS partials -> one __syncthreads -> warp0 lanes 0-7 finalize + tagged store.

#define S     1024
#define NOBS  4096
#define TT    8192
#define KCTA  128
#define CCOL  8
#define NTHR  256

__device__ __align__(16) float        g_emitT[TT * S];  // exp(emit[j, obs[t]]), [t][j]
__device__ __align__(16) unsigned int g_w[2][S];        // sign-tagged positive floats

__device__ __forceinline__ uint4 ld_vol_v4(const unsigned int* p) {
    uint4 v;
    asm volatile("ld.volatile.global.v4.u32 {%0,%1,%2,%3}, [%4];"
                 : "=r"(v.x), "=r"(v.y), "=r"(v.z), "=r"(v.w) : "l"(p) : "memory");
    return v;
}
__device__ __forceinline__ void st_rel_u32(unsigned int* p, unsigned int v) {
    asm volatile("st.relaxed.gpu.global.u32 [%0], %1;" :: "l"(p), "r"(v) : "memory");
}

// Prologue: gather exp(emit) per timestep; w0 into buffer 0 with sign tag 0.
__global__ void hmm_init_kernel(const int* __restrict__ obs,
                                const float* __restrict__ start,
                                const float* __restrict__ emit) {
    long idx = (long)blockIdx.x * blockDim.x + threadIdx.x;
    if (idx >= (long)TT * S) return;
    int t = (int)(idx >> 10);
    int j = (int)(idx & (S - 1));
    float e = expf(emit[(long)j * NOBS + obs[t]]);
    g_emitT[idx] = e;
    if (t == 0) {
        float v = fmaxf(expf(start[j]) * e, 1e-33f);
        g_w[0][j] = __float_as_uint(v);      // sign 0 == phase of t=0
    }
}

__global__ void __launch_bounds__(NTHR, 1)
hmm_main_kernel(const float* __restrict__ trans, float* __restrict__ out) {
    __shared__ float red_s[2][NTHR / 32][CCOL];   // per-warp partials, parity-buffered
    __shared__ float max_s[NTHR / 32];

    const int tid  = threadIdx.x;
    const int lane = tid & 31;
    const int wid  = tid >> 5;
    const int cta  = blockIdx.x;
    const int j0   = cta * CCOL;
    const int i0   = tid << 2;                    // this thread's 4 source states

    // P slice in registers: P[c][u] = exp(trans[i0+u][j0+c]).
    float P[CCOL][4];
    #pragma unroll
    for (int u = 0; u < 4; ++u) {
        #pragma unroll
        for (int c = 0; c < CCOL; ++c)
            P[c][u] = expf(__ldg(&trans[(long)(i0 + u) * S + j0 + c]));
    }

    float e_c = 0.0f, e_n = 0.0f, e_n2 = 0.0f;
    if (tid < CCOL) {
        e_c = __ldg(&g_emitT[1 * S + j0 + tid]);
        e_n = __ldg(&g_emitT[(TT > 2 ? 2 : 1) * S + j0 + tid]);
    }

    float logscale = 0.0f;    // meaningful on tid<CCOL (identical there)

    for (int t = 1; t < TT; ++t) {
        const int      rb    = (t - 1) & 1;
        const int      par   = t & 1;
        const unsigned esbit = (((unsigned)(t - 1) >> 1) & 1u) << 31;
        const unsigned int* gp = &g_w[rb][i0];

        // ---- Poll own granule: the data IS the sync ----
        float w0, w1, w2, w3;
        for (;;) {
            uint4 v = ld_vol_v4(gp);
            unsigned bad = ((v.x ^ esbit) | (v.y ^ esbit) |
                            (v.z ^ esbit) | (v.w ^ esbit)) & 0x80000000u;
            if (!bad) {
                w0 = __uint_as_float(v.x & 0x7fffffffu);
                w1 = __uint_as_float(v.y & 0x7fffffffu);
                w2 = __uint_as_float(v.z & 0x7fffffffu);
                w3 = __uint_as_float(v.w & 0x7fffffffu);
                break;
            }
        }

        // Emission prefetch, two steps deep (hides DRAM latency of g_emitT).
        if (tid < CCOL) {
            int tn = (t + 2 < TT) ? t + 2 : TT - 1;
            e_n2 = __ldg(&g_emitT[tn * S + j0 + tid]);
        }

        // ---- Rescale pre-pass (every 8th step): per-warp max to SMEM ----
        const bool resc = ((t - 1) & 7) == 0;
        if (resc) {
            float m = fmaxf(fmaxf(w0, w1), fmaxf(w2, w3));
            #pragma unroll
            for (int off = 16; off; off >>= 1)
                m = fmaxf(m, __shfl_xor_sync(0xffffffffu, m, off));
            if (lane == 0) max_s[wid] = m;
        }

        // ---- GEMV: 32 FFMA, 8 independent chains ----
        float acc[CCOL];
        #pragma unroll
        for (int c = 0; c < CCOL; ++c)
            acc[c] = w0 * P[c][0] + w1 * P[c][1] + w2 * P[c][2] + w3 * P[c][3];

        #pragma unroll
        for (int off = 16; off; off >>= 1) {
            #pragma unroll
            for (int c = 0; c < CCOL; ++c)
                acc[c] += __shfl_xor_sync(0xffffffffu, acc[c], off);
        }
        if (lane == 0) {
            #pragma unroll
            for (int c = 0; c < CCOL; ++c) red_s[par][wid][c] = acc[c];
        }
        __syncthreads();

        // ---- Finalize: warp0 lanes 0-7 own the CTA's 8 columns ----
        if (tid < CCOL) {
            float inv = 1.0f;
            if (resc) {
                float m = max_s[0];
                #pragma unroll
                for (int ww = 1; ww < NTHR / 32; ++ww) m = fmaxf(m, max_s[ww]);
                inv = 1.0f / m;
                logscale += __logf(m);
            }
            float s = 0.0f;
            #pragma unroll
            for (int ww = 0; ww < NTHR / 32; ++ww) s += red_s[par][ww][tid];
            float outv = fmaxf(s * inv * e_c, 1e-33f);
            unsigned tag = (((unsigned)t >> 1) & 1u) << 31;
            st_rel_u32(&g_w[t & 1][j0 + tid], __float_as_uint(outv) | tag);
            e_c = e_n;
            e_n = e_n2;
        }
    }

    // ---- Epilogue: CTA 0 polls the final vector and reduces ----
    if (cta == 0) {
        const unsigned esbit = (((unsigned)(TT - 1) >> 1) & 1u) << 31;
        const unsigned int* gp = &g_w[(TT - 1) & 1][i0];
        float w0, w1, w2, w3;
        for (;;) {
            uint4 v = ld_vol_v4(gp);
            unsigned bad = ((v.x ^ esbit) | (v.y ^ esbit) |
                            (v.z ^ esbit) | (v.w ^ esbit)) & 0x80000000u;
            if (!bad) {
                w0 = __uint_as_float(v.x & 0x7fffffffu);
                w1 = __uint_as_float(v.y & 0x7fffffffu);
                w2 = __uint_as_float(v.z & 0x7fffffffu);
                w3 = __uint_as_float(v.w & 0x7fffffffu);
                break;
            }
        }
        float s = w0 + w1 + w2 + w3;
        #pragma unroll
        for (int off = 16; off; off >>= 1)
            s += __shfl_xor_sync(0xffffffffu, s, off);
        __shared__ float fin_s[NTHR / 32];
        if (lane == 0) fin_s[wid] = s;
        __syncthreads();
        if (tid == 0) {
            float tot = 0.0f;
            #pragma unroll
            for (int ww = 0; ww < NTHR / 32; ++ww) tot += fin_s[ww];
            out[0] = logf(tot) + logscale;
        }
    }
}

extern "C" void kernel_launch(void* const* d_in, const int* in_sizes, int n_in,
                              void* d_out, int out_size) {
    const int*   obs   = (const int*)d_in[0];
    const float* start = (const float*)d_in[1];
    const float* trans = (const float*)d_in[2];
    const float* emit  = (const float*)d_in[3];
    float*       out   = (float*)d_out;

    (void)in_sizes; (void)n_in; (void)out_size;

    const int init_blocks = (TT * S + 255) / 256;
    hmm_init_kernel<<<init_blocks, 256>>>(obs, start, emit);
    hmm_main_kernel<<<KCTA, NTHR>>>(trans, out);
}